// round 14
// baseline (speedup 1.0000x reference)
#include <cuda_runtime.h>
#include <cstdint>
#include <cmath>

// ---------------------------------------------------------------------------
// SpatialPatchMoE round 14: round-13 base (403.5us) + fused dwconv+LN in
// registers (quad shfl reduction), barrier dieting (12 -> 8 per block),
// conflict-free staggered H stores, expert-2 staging overlapped with dwconv.
// ---------------------------------------------------------------------------

#define NPATCH 512
typedef unsigned long long ull;

// smem layout (floats)
#define XS_CP   132                  // xs: [64ch][8*16+4] = 8448
#define H_OFF   8448                 // H [64 pos][64 ch] pitch 68 -> 4352
#define H_P     68
#define WG_OFF  12800                // W1 [64k][136] = 8704 (aliased w/ XG [64][68])
#define W1_P    136
#define XG_P    68
#define W2_OFF  21504                // W2 [64k][72] = 4608
#define W2_P    72
#define SMEM_FLOATS 26112            // 104448 bytes -> 2 blocks/SM

__device__ int   g_topi[NPATCH][2];
__device__ float g_topw[NPATCH][2];
__device__ __align__(16) float g_w1f[8][64*W1_P];  // [e][c][n'=2o|2o+1] tf32
__device__ __align__(16) float g_w2f[8][64*W2_P];  // [e][c][o] tf32

// ---- f32x2 / tf32 helpers ----
__device__ __forceinline__ ull pk2(float lo, float hi) {
    ull r; asm("mov.b64 %0, {%1, %2};" : "=l"(r) : "f"(lo), "f"(hi)); return r;
}
__device__ __forceinline__ ull dup2(float v) {
    ull r; asm("mov.b64 %0, {%1, %1};" : "=l"(r) : "f"(v)); return r;
}
__device__ __forceinline__ void fma2(ull& d, ull a, ull b) {
    asm("fma.rn.f32x2 %0, %1, %2, %0;" : "+l"(d) : "l"(a), "l"(b));
}
__device__ __forceinline__ float2 up2(ull v) {
    float2 f; asm("mov.b64 {%0, %1}, %2;" : "=f"(f.x), "=f"(f.y) : "l"(v)); return f;
}
__device__ __forceinline__ float to_tf32(float x) {
    uint32_t r; asm("cvt.rna.tf32.f32 %0, %1;" : "=r"(r) : "f"(x));
    return __uint_as_float(r);
}
__device__ __forceinline__ void mma8(float* d, uint32_t a0, uint32_t a1,
                                     uint32_t a2, uint32_t a3,
                                     uint32_t b0, uint32_t b1) {
    asm volatile(
        "mma.sync.aligned.m16n8k8.row.col.f32.tf32.tf32.f32 "
        "{%0,%1,%2,%3}, {%4,%5,%6,%7}, {%8,%9}, {%0,%1,%2,%3};"
        : "+f"(d[0]), "+f"(d[1]), "+f"(d[2]), "+f"(d[3])
        : "r"(a0), "r"(a1), "r"(a2), "r"(a3), "r"(b0), "r"(b1));
}
__device__ __forceinline__ uint32_t fu(float x) { return __float_as_uint(x); }

// ---------------------------------------------------------------------------
// Pre-pass (grid 64): tf32 weights; W1 a/g-interleaved+transposed, W2 transposed
// ---------------------------------------------------------------------------
__global__ __launch_bounds__(256) void prepass_kernel(
    const float* __restrict__ pwi_w, const float* __restrict__ pwo_w)
{
    int blk = blockIdx.x, e = blk >> 3, part = blk & 7, t = threadIdx.x;
    const float* s1 = pwi_w + (long)e*8192;
    float* d1 = g_w1f[e];
    for (int i = part*1024 + t; i < part*1024 + 1024; i += 256) {
        int o = i >> 6, c = i & 63;
        int np = (o < 64) ? (2*o) : (2*(o-64) + 1);
        d1[c*W1_P + np] = to_tf32(s1[i]);
    }
    const float* s2 = pwo_w + (long)e*4096;
    float* d2 = g_w2f[e];
    for (int i = part*512 + t; i < part*512 + 512; i += 256) {
        int o = i >> 6, c = i & 63;
        d2[c*W2_P + o] = to_tf32(s2[i]);
    }
}

// ---------------------------------------------------------------------------
// Router (unchanged, proven)
// ---------------------------------------------------------------------------
__global__ __launch_bounds__(256) void router_kernel(
    const float* __restrict__ x,
    const float* __restrict__ rw,
    const float* __restrict__ rb)
{
    int n  = blockIdx.x;
    int b  = n >> 8;
    int ph = (n >> 4) & 15;
    int pw = n & 15;
    int t = threadIdx.x, lane = t & 31, warp = t >> 5;
    int i4 = lane >> 3, j = lane & 7;

    __shared__ float sm[64];
    __shared__ float logits[8];

    for (int r = 0; r < 8; ++r) {
        int c = warp * 8 + r;
        const float* xc = x + ((long)b*64 + c)*131072 + (ph*8)*128 + pw*8;
        float s = 0.f;
        #pragma unroll
        for (int l = 0; l < 8; ++l) {
            long base = (long)l * 16384;
            s += xc[base + i4*128 + j];
            s += xc[base + (i4+4)*128 + j];
        }
        #pragma unroll
        for (int off = 16; off; off >>= 1) s += __shfl_xor_sync(0xFFFFFFFFu, s, off);
        if (lane == 0) sm[c] = s * (1.f/512.f);
    }
    __syncthreads();
    if (t < 8) {
        float acc = rb[t];
        const float* w = rw + t*64;
        #pragma unroll
        for (int c = 0; c < 64; ++c) acc += sm[c] * w[c];
        logits[t] = acc;
    }
    __syncthreads();
    if (t == 0) {
        int i0 = 0; float v0 = logits[0];
        #pragma unroll
        for (int e = 1; e < 8; ++e) if (logits[e] > v0) { v0 = logits[e]; i0 = e; }
        int i1 = -1; float v1 = -3.4e38f;
        #pragma unroll
        for (int e = 0; e < 8; ++e) if (e != i0 && logits[e] > v1) { v1 = logits[e]; i1 = e; }
        float e1  = __expf(v1 - v0);
        float inv = 1.f / (1.f + e1);
        g_topi[n][0] = i0; g_topi[n][1] = i1;
        g_topw[n][0] = inv; g_topw[n][1] = e1 * inv;
    }
}

// ---------------------------------------------------------------------------
// Main kernel: grid 4096 = (patch, l); 256 threads = 8 warps; 2 blocks/SM.
// ---------------------------------------------------------------------------
extern __shared__ float smem_dyn[];

__device__ __forceinline__ void stage_weights(int e, int t, float* WG, float* W2s)
{
    const float4* s1 = (const float4*)g_w1f[e];
    float4* d1 = (float4*)WG;
    #pragma unroll
    for (int i = 0; i < 9; ++i) {             // ceil(2176/256) = 9
        int idx = t + i*256;
        if (idx < 2176) d1[idx] = s1[idx];
    }
    const float4* s2 = (const float4*)g_w2f[e];
    float4* d2 = (float4*)W2s;
    #pragma unroll
    for (int i = 0; i < 5; ++i) {             // ceil(1152/256) = 5
        int idx = t + i*256;
        if (idx < 1152) d2[idx] = s2[idx];
    }
}

__global__ __launch_bounds__(256, 2) void moe_kernel(
    const float* __restrict__ x,
    const float* __restrict__ dw_w,  const float* __restrict__ dw_b,
    const float* __restrict__ ln_w,  const float* __restrict__ ln_b,
    const float* __restrict__ pwi_b, const float* __restrict__ pwo_b,
    float* __restrict__ out)
{
    float* xs  = smem_dyn;              // [64ch][132] persists both experts
    float* H   = smem_dyn + H_OFF;      // [64 pos][68]
    float* WG  = smem_dyn + WG_OFF;     // W1 [64k][136], then XG [64pos][68]
    float* W2s = smem_dyn + W2_OFF;     // [64k][72]

    int s = blockIdx.x;
    int n = s >> 3, l = s & 7;
    int b = n >> 8, ph = (n >> 4) & 15, pwn = n & 15;
    int t = threadIdx.x, lane = t & 31, wid = t >> 5;

    const long gbase = (long)b*64*131072 + (long)l*16384 + (ph*8)*128 + pwn*8;

    int   e0 = g_topi[n][0], e1i = g_topi[n][1];
    float wgt0 = g_topw[n][0], wgt1 = g_topw[n][1];

    // warp MMA tiling
    const int gid = lane >> 2;              // 0..7
    const int tig = lane & 3;               // 0..3
    const int mt  = wid & 3;                // m-tile (16 positions)
    const int nh  = wid >> 2;               // n-half (0..1)
    const int r0  = mt*16 + gid, r1 = r0 + 8;

    // dwconv/LN per-thread assignment: quad (t&3) covers channel t>>2
    const int dc_c  = t >> 2;               // channel 0..63
    const int dc_q  = t & 3;                // quad index
    const int dc_rr = dc_q * 2;             // output rows rr, rr+1

    float osum[4][4];
    #pragma unroll
    for (int jt = 0; jt < 4; ++jt)
        #pragma unroll
        for (int q = 0; q < 4; ++q) osum[jt][q] = 0.f;

    // ---- one-time xs load + expert-0 weight staging ------------------------
    stage_weights(e0, t, WG, W2s);
    for (int rid = t; rid < 512; rid += 256) {
        float* row = xs + (rid >> 3)*XS_CP + (rid & 7)*16;
        row[0] = 0.f; row[1] = 0.f; row[2] = 0.f;
        row[11] = 0.f; row[12] = 0.f; row[13] = 0.f;
    }
    for (int idx = t; idx < 4096; idx += 256) {
        int c = idx >> 6, p = idx & 63, i = p >> 3, j = p & 7;
        xs[c*XS_CP + i*16 + 3 + j] = x[gbase + (long)c*131072 + i*128 + j];
    }
    __syncthreads();

    for (int kk = 0; kk < 2; ++kk) {
        const int   e  = kk ? e1i : e0;
        const float we = kk ? wgt1 : wgt0;

        // ---- fused dwconv 7x7 + LayerNorm (all in registers) -> H (tf32) --
        {
            const float* W = dw_w + ((long)e*64 + dc_c)*49;
            float bias = __ldg(&dw_b[e*64 + dc_c]);
            ull acc[8];
            #pragma unroll
            for (int j = 0; j < 8; ++j) acc[j] = dup2(bias);

            float wprev[7];
            #pragma unroll
            for (int u = 0; u < 7; ++u) wprev[u] = 0.f;

            #pragma unroll
            for (int di = 0; di < 8; ++di) {
                float wcur[7];
                #pragma unroll
                for (int u = 0; u < 7; ++u)
                    wcur[u] = (di <= 6) ? __ldg(&W[di*7 + u]) : 0.f;
                int ii = dc_rr + di - 3;
                if (ii >= 0 && ii <= 7) {
                    const float* xr = xs + dc_c*XS_CP + ii*16;
                    float4 v0 = *(const float4*)(xr);
                    float4 v1 = *(const float4*)(xr + 4);
                    float4 v2 = *(const float4*)(xr + 8);
                    float4 v3 = *(const float4*)(xr + 12);
                    float win[14] = {v0.x,v0.y,v0.z,v0.w, v1.x,v1.y,v1.z,v1.w,
                                     v2.x,v2.y,v2.z,v2.w, v3.x,v3.y};
                    ull wd[14];
                    #pragma unroll
                    for (int u = 0; u < 14; ++u) wd[u] = dup2(win[u]);
                    #pragma unroll
                    for (int dj = 0; dj < 7; ++dj) {
                        ull wp = pk2(wcur[dj], wprev[dj]);
                        #pragma unroll
                        for (int j = 0; j < 8; ++j) fma2(acc[j], wp, wd[dj + j]);
                    }
                }
                #pragma unroll
                for (int u = 0; u < 7; ++u) wprev[u] = wcur[u];
            }

            // unpack: a0 = row dc_rr (pos dc_rr*8+j), a1 = row dc_rr+1
            float a0[8], a1[8];
            float sum = 0.f, sq = 0.f;
            #pragma unroll
            for (int j = 0; j < 8; ++j) {
                float2 f = up2(acc[j]);
                a0[j] = f.x; a1[j] = f.y;
                sum += f.x + f.y;
                sq  += f.x*f.x + f.y*f.y;
            }
            // quad reduction over the channel's 64 positions
            sum += __shfl_xor_sync(0xFFFFFFFFu, sum, 1);
            sq  += __shfl_xor_sync(0xFFFFFFFFu, sq, 1);
            sum += __shfl_xor_sync(0xFFFFFFFFu, sum, 2);
            sq  += __shfl_xor_sync(0xFFFFFFFFu, sq, 2);
            float mu   = sum * (1.f/64.f);
            float var  = sq  * (1.f/64.f) - mu*mu;
            float rstd = rsqrtf(var + 1e-5f);

            const float* lw = ln_w + e*64;
            const float* lb = ln_b + e*64;
            // staggered stores: j' = (u + 2q) & 7 -> 32 distinct banks
            #pragma unroll
            for (int u = 0; u < 8; ++u) {
                int j = (u + 2*dc_q) & 7;
                int pos0 = dc_rr*8 + j;
                int pos1 = pos0 + 8;
                float v0 = (a0[j] - mu) * rstd * __ldg(&lw[pos0]) + __ldg(&lb[pos0]);
                float v1 = (a1[j] - mu) * rstd * __ldg(&lw[pos1]) + __ldg(&lb[pos1]);
                H[pos0*H_P + dc_c] = to_tf32(v0);
                H[pos1*H_P + dc_c] = to_tf32(v1);
            }
        }
        __syncthreads();   // H ready + staging(e) visible

        // ---- GEMM1 mma: D1[64 x 128(int)] = H x W1(WG) --------------------
        float ac1[8][4];
        {
            #pragma unroll
            for (int jt = 0; jt < 8; ++jt)
                #pragma unroll
                for (int q = 0; q < 4; ++q) ac1[jt][q] = 0.f;

            #pragma unroll
            for (int ks = 0; ks < 8; ++ks) {
                int k0 = ks*8 + tig, k1 = k0 + 4;
                uint32_t a0 = fu(H[r0*H_P + k0]);
                uint32_t a1 = fu(H[r1*H_P + k0]);
                uint32_t a2 = fu(H[r0*H_P + k1]);
                uint32_t a3 = fu(H[r1*H_P + k1]);
                #pragma unroll
                for (int jt = 0; jt < 8; ++jt) {
                    int nb = nh*64 + jt*8 + gid;
                    uint32_t b0 = fu(WG[k0*W1_P + nb]);
                    uint32_t b1 = fu(WG[k1*W1_P + nb]);
                    mma8(ac1[jt], a0, a1, a2, a3, b0, b1);
                }
            }
        }
        __syncthreads();   // all W1 reads done before XG overwrites WG

        // ---- GLU in regs -> XG (aliased over W1 region) -------------------
        {
            const float* bi = pwi_b + e*128;
            #pragma unroll
            for (int jt = 0; jt < 8; ++jt) {
                int o = nh*32 + jt*4 + tig;
                float ba = __ldg(&bi[o]), bg = __ldg(&bi[64 + o]);
                float a = ac1[jt][0] + ba, g = ac1[jt][1] + bg;
                WG[r0*XG_P + o] = to_tf32(a * (1.f/(1.f + __expf(-a))) * g);
                a = ac1[jt][2] + ba; g = ac1[jt][3] + bg;
                WG[r1*XG_P + o] = to_tf32(a * (1.f/(1.f + __expf(-a))) * g);
            }
        }
        __syncthreads();

        // ---- GEMM2: D2[64 x 64] = XG x W2 -> osum (weighted) --------------
        {
            float ac[4][4];
            #pragma unroll
            for (int jt = 0; jt < 4; ++jt)
                #pragma unroll
                for (int q = 0; q < 4; ++q) ac[jt][q] = 0.f;

            #pragma unroll
            for (int ks = 0; ks < 8; ++ks) {
                int k0 = ks*8 + tig, k1 = k0 + 4;
                uint32_t a0 = fu(WG[r0*XG_P + k0]);
                uint32_t a1 = fu(WG[r1*XG_P + k0]);
                uint32_t a2 = fu(WG[r0*XG_P + k1]);
                uint32_t a3 = fu(WG[r1*XG_P + k1]);
                #pragma unroll
                for (int jt = 0; jt < 4; ++jt) {
                    int nb = nh*32 + jt*8 + gid;
                    uint32_t b0 = fu(W2s[k0*W2_P + nb]);
                    uint32_t b1 = fu(W2s[k1*W2_P + nb]);
                    mma8(ac[jt], a0, a1, a2, a3, b0, b1);
                }
            }
            const float* bo = pwo_b + e*64;
            #pragma unroll
            for (int jt = 0; jt < 4; ++jt) {
                int c0 = nh*32 + jt*8 + tig*2;
                float b0 = __ldg(&bo[c0]), b1 = __ldg(&bo[c0+1]);
                osum[jt][0] += we * (ac[jt][0] + b0);
                osum[jt][1] += we * (ac[jt][1] + b1);
                osum[jt][2] += we * (ac[jt][2] + b0);
                osum[jt][3] += we * (ac[jt][3] + b1);
            }
        }

        if (kk == 0) {
            __syncthreads();              // XG/W2s reads done -> restage safe
            stage_weights(e1i, t, WG, W2s);  // overlaps next dwconv
        }
    }

    // ---- out = x + sum_e we*h_e  (residual from persistent xs) -----------
    {
        int i0 = r0 >> 3, j0 = r0 & 7;     // pos r0
        int i1 = r1 >> 3, j1 = r1 & 7;     // pos r1
        #pragma unroll
        for (int jt = 0; jt < 4; ++jt) {
            int c0 = nh*32 + jt*8 + tig*2;
            float x00 = xs[c0*XS_CP     + i0*16 + 3 + j0];
            float x01 = xs[(c0+1)*XS_CP + i0*16 + 3 + j0];
            float x10 = xs[c0*XS_CP     + i1*16 + 3 + j1];
            float x11 = xs[(c0+1)*XS_CP + i1*16 + 3 + j1];
            long idx00 = gbase + (long)c0*131072     + i0*128 + j0;
            long idx01 = gbase + (long)(c0+1)*131072 + i0*128 + j0;
            long idx10 = gbase + (long)c0*131072     + i1*128 + j1;
            long idx11 = gbase + (long)(c0+1)*131072 + i1*128 + j1;
            out[idx00] = x00 + osum[jt][0];
            out[idx01] = x01 + osum[jt][1];
            out[idx10] = x10 + osum[jt][2];
            out[idx11] = x11 + osum[jt][3];
        }
    }
}

// ---------------------------------------------------------------------------
extern "C" void kernel_launch(void* const* d_in, const int* in_sizes, int n_in,
                              void* d_out, int out_size)
{
    const float* x        = (const float*)d_in[0];
    const float* router_w = (const float*)d_in[1];
    const float* router_b = (const float*)d_in[2];
    const float* dw_w     = (const float*)d_in[3];
    const float* dw_b     = (const float*)d_in[4];
    const float* ln_w     = (const float*)d_in[5];
    const float* ln_b     = (const float*)d_in[6];
    const float* pwi_w    = (const float*)d_in[7];
    const float* pwi_b    = (const float*)d_in[8];
    const float* pwo_w    = (const float*)d_in[9];
    const float* pwo_b    = (const float*)d_in[10];
    float* out = (float*)d_out;

    prepass_kernel<<<64, 256>>>(pwi_w, pwo_w);
    router_kernel<<<NPATCH, 256>>>(x, router_w, router_b);

    const int smem_bytes = SMEM_FLOATS * sizeof(float);   // 104448
    cudaFuncSetAttribute(moe_kernel,
                         cudaFuncAttributeMaxDynamicSharedMemorySize, smem_bytes);
    moe_kernel<<<4096, 256, smem_bytes>>>(x, dw_w, dw_b, ln_w, ln_b,
                                          pwi_b, pwo_b, out);
}

// round 15
// speedup vs baseline: 1.0333x; 1.0333x over previous
#include <cuda_runtime.h>
#include <cstdint>
#include <cmath>

// ---------------------------------------------------------------------------
// SpatialPatchMoE round 15: revert to round-13 moe_kernel (403.5us proven;
// round-14 fusion regressed to 413.6). Merge prepass INTO router_kernel:
// 2 launches per call -> ncu -s5 lands on moe_kernel next round, and the
// 5.7us serial prepass disappears.
// ---------------------------------------------------------------------------

#define NPATCH 512
typedef unsigned long long ull;

// smem layout (floats)
#define XS_CP   132                  // xs: [64ch][8*16+4] = 8448
#define H_OFF   8448                 // H [64 pos][64 ch] pitch 68 -> 4352
#define H_P     68
#define WG_OFF  12800                // W1 [64k][136] = 8704 (aliased w/ XG [64][68])
#define W1_P    136
#define XG_P    68
#define W2_OFF  21504                // W2 [64k][72] = 4608
#define W2_P    72
#define SMEM_FLOATS 26112            // 104448 bytes -> 2 blocks/SM

__device__ int   g_topi[NPATCH][2];
__device__ float g_topw[NPATCH][2];
__device__ __align__(16) float g_w1f[8][64*W1_P];  // [e][c][n'=2o|2o+1] tf32
__device__ __align__(16) float g_w2f[8][64*W2_P];  // [e][c][o] tf32

// ---- f32x2 / tf32 helpers ----
__device__ __forceinline__ ull pk2(float lo, float hi) {
    ull r; asm("mov.b64 %0, {%1, %2};" : "=l"(r) : "f"(lo), "f"(hi)); return r;
}
__device__ __forceinline__ ull dup2(float v) {
    ull r; asm("mov.b64 %0, {%1, %1};" : "=l"(r) : "f"(v)); return r;
}
__device__ __forceinline__ void fma2(ull& d, ull a, ull b) {
    asm("fma.rn.f32x2 %0, %1, %2, %0;" : "+l"(d) : "l"(a), "l"(b));
}
__device__ __forceinline__ float2 up2(ull v) {
    float2 f; asm("mov.b64 {%0, %1}, %2;" : "=f"(f.x), "=f"(f.y) : "l"(v)); return f;
}
__device__ __forceinline__ float to_tf32(float x) {
    uint32_t r; asm("cvt.rna.tf32.f32 %0, %1;" : "=r"(r) : "f"(x));
    return __uint_as_float(r);
}
__device__ __forceinline__ void mma8(float* d, uint32_t a0, uint32_t a1,
                                     uint32_t a2, uint32_t a3,
                                     uint32_t b0, uint32_t b1) {
    asm volatile(
        "mma.sync.aligned.m16n8k8.row.col.f32.tf32.tf32.f32 "
        "{%0,%1,%2,%3}, {%4,%5,%6,%7}, {%8,%9}, {%0,%1,%2,%3};"
        : "+f"(d[0]), "+f"(d[1]), "+f"(d[2]), "+f"(d[3])
        : "r"(a0), "r"(a1), "r"(a2), "r"(a3), "r"(b0), "r"(b1));
}
__device__ __forceinline__ uint32_t fu(float x) { return __float_as_uint(x); }

// ---------------------------------------------------------------------------
// Router + weight prepass merged (grid 512). Router part unchanged.
// Prepass spread over blocks: e = blk>>6, part = blk&63 ->
//   128 W1 elements + 64 W2 elements per block (<=1 per thread each).
// ---------------------------------------------------------------------------
__global__ __launch_bounds__(256) void router_kernel(
    const float* __restrict__ x,
    const float* __restrict__ rw,
    const float* __restrict__ rb,
    const float* __restrict__ pwi_w,
    const float* __restrict__ pwo_w)
{
    int n  = blockIdx.x;
    int b  = n >> 8;
    int ph = (n >> 4) & 15;
    int pw = n & 15;
    int t = threadIdx.x, lane = t & 31, warp = t >> 5;
    int i4 = lane >> 3, j = lane & 7;

    // ---- distributed weight prepass (independent of router work) ----
    {
        int e = n >> 6, part = n & 63;
        if (t < 128) {
            int i = part*128 + t;                   // W1: 8192/64 = 128 per block
            int o = i >> 6, c = i & 63;
            int np = (o < 64) ? (2*o) : (2*(o-64) + 1);
            g_w1f[e][c*W1_P + np] = to_tf32(pwi_w[(long)e*8192 + i]);
        } else if (t < 192) {
            int i = part*64 + (t - 128);            // W2: 4096/64 = 64 per block
            int o = i >> 6, c = i & 63;
            g_w2f[e][c*W2_P + o] = to_tf32(pwo_w[(long)e*4096 + i]);
        }
    }

    __shared__ float sm[64];
    __shared__ float logits[8];

    for (int r = 0; r < 8; ++r) {
        int c = warp * 8 + r;
        const float* xc = x + ((long)b*64 + c)*131072 + (ph*8)*128 + pw*8;
        float s = 0.f;
        #pragma unroll
        for (int l = 0; l < 8; ++l) {
            long base = (long)l * 16384;
            s += xc[base + i4*128 + j];
            s += xc[base + (i4+4)*128 + j];
        }
        #pragma unroll
        for (int off = 16; off; off >>= 1) s += __shfl_xor_sync(0xFFFFFFFFu, s, off);
        if (lane == 0) sm[c] = s * (1.f/512.f);
    }
    __syncthreads();
    if (t < 8) {
        float acc = rb[t];
        const float* w = rw + t*64;
        #pragma unroll
        for (int c = 0; c < 64; ++c) acc += sm[c] * w[c];
        logits[t] = acc;
    }
    __syncthreads();
    if (t == 0) {
        int i0 = 0; float v0 = logits[0];
        #pragma unroll
        for (int e = 1; e < 8; ++e) if (logits[e] > v0) { v0 = logits[e]; i0 = e; }
        int i1 = -1; float v1 = -3.4e38f;
        #pragma unroll
        for (int e = 0; e < 8; ++e) if (e != i0 && logits[e] > v1) { v1 = logits[e]; i1 = e; }
        float e1  = __expf(v1 - v0);
        float inv = 1.f / (1.f + e1);
        g_topi[n][0] = i0; g_topi[n][1] = i1;
        g_topw[n][0] = inv; g_topw[n][1] = e1 * inv;
    }
}

// ---------------------------------------------------------------------------
// Main kernel: grid 4096 = (patch, l); 256 threads = 8 warps; 2 blocks/SM.
// (= round-13 kernel, byte-identical logic)
// ---------------------------------------------------------------------------
extern __shared__ float smem_dyn[];

__global__ __launch_bounds__(256, 2) void moe_kernel(
    const float* __restrict__ x,
    const float* __restrict__ dw_w,  const float* __restrict__ dw_b,
    const float* __restrict__ ln_w,  const float* __restrict__ ln_b,
    const float* __restrict__ pwi_b, const float* __restrict__ pwo_b,
    float* __restrict__ out)
{
    float* xs  = smem_dyn;              // [64ch][132] persists both experts
    float* H   = smem_dyn + H_OFF;      // [64 pos][68]
    float* WG  = smem_dyn + WG_OFF;     // W1 [64k][136], then XG [64pos][68]
    float* W2s = smem_dyn + W2_OFF;     // [64k][72]

    int s = blockIdx.x;
    int n = s >> 3, l = s & 7;
    int b = n >> 8, ph = (n >> 4) & 15, pwn = n & 15;
    int t = threadIdx.x, lane = t & 31, wid = t >> 5;

    const long gbase = (long)b*64*131072 + (long)l*16384 + (ph*8)*128 + pwn*8;

    int   e0 = g_topi[n][0], e1i = g_topi[n][1];
    float wgt0 = g_topw[n][0], wgt1 = g_topw[n][1];

    // warp MMA tiling
    const int gid = lane >> 2;              // 0..7
    const int tig = lane & 3;               // 0..3
    const int mt  = wid & 3;                // m-tile (16 positions)
    const int nh  = wid >> 2;               // n-half (0..1)
    const int r0  = mt*16 + gid, r1 = r0 + 8;

    // dwconv per-thread assignment
    const int dc_c  = t >> 2;               // channel 0..63
    const int dc_rr = (t & 3) * 2;          // output rows rr, rr+1

    float osum[4][4];
    #pragma unroll
    for (int jt = 0; jt < 4; ++jt)
        #pragma unroll
        for (int q = 0; q < 4; ++q) osum[jt][q] = 0.f;

    // ---- one-time xs load (persists across both experts) ------------------
    for (int rid = t; rid < 512; rid += 256) {
        float* row = xs + (rid >> 3)*XS_CP + (rid & 7)*16;
        row[0] = 0.f; row[1] = 0.f; row[2] = 0.f;
        row[11] = 0.f; row[12] = 0.f; row[13] = 0.f;
    }
    for (int idx = t; idx < 4096; idx += 256) {
        int c = idx >> 6, p = idx & 63, i = p >> 3, j = p & 7;
        xs[c*XS_CP + i*16 + 3 + j] = x[gbase + (long)c*131072 + i*128 + j];
    }

    for (int kk = 0; kk < 2; ++kk) {
        const int   e  = kk ? e1i : e0;
        const float we = kk ? wgt1 : wgt0;

        // ---- stage W1(e) into WG (2176 float4), W2(e) into W2s (1152) -----
        {
            const float4* s1 = (const float4*)g_w1f[e];
            float4* d1 = (float4*)WG;
            #pragma unroll
            for (int i = 0; i < 9; ++i) {             // ceil(2176/256) = 9
                int idx = t + i*256;
                if (idx < 2176) d1[idx] = s1[idx];
            }
            const float4* s2 = (const float4*)g_w2f[e];
            float4* d2 = (float4*)W2s;
            #pragma unroll
            for (int i = 0; i < 5; ++i) {             // ceil(1152/256) = 5
                int idx = t + i*256;
                if (idx < 1152) d2[idx] = s2[idx];
            }
        }
        __syncthreads();   // xs (kk=0) + staging visible

        // ---- dwconv 7x7 (f32x2 over row pair) -> H[pos][ch] ---------------
        {
            const float* W = dw_w + ((long)e*64 + dc_c)*49;
            float bias = __ldg(&dw_b[e*64 + dc_c]);
            ull acc[8];
            #pragma unroll
            for (int j = 0; j < 8; ++j) acc[j] = dup2(bias);

            float wprev[7];
            #pragma unroll
            for (int u = 0; u < 7; ++u) wprev[u] = 0.f;

            #pragma unroll
            for (int di = 0; di < 8; ++di) {
                float wcur[7];
                #pragma unroll
                for (int u = 0; u < 7; ++u)
                    wcur[u] = (di <= 6) ? __ldg(&W[di*7 + u]) : 0.f;
                int ii = dc_rr + di - 3;
                if (ii >= 0 && ii <= 7) {
                    const float* xr = xs + dc_c*XS_CP + ii*16;
                    float4 v0 = *(const float4*)(xr);
                    float4 v1 = *(const float4*)(xr + 4);
                    float4 v2 = *(const float4*)(xr + 8);
                    float4 v3 = *(const float4*)(xr + 12);
                    float win[14] = {v0.x,v0.y,v0.z,v0.w, v1.x,v1.y,v1.z,v1.w,
                                     v2.x,v2.y,v2.z,v2.w, v3.x,v3.y};
                    ull wd[14];
                    #pragma unroll
                    for (int u = 0; u < 14; ++u) wd[u] = dup2(win[u]);
                    #pragma unroll
                    for (int dj = 0; dj < 7; ++dj) {
                        ull wp = pk2(wcur[dj], wprev[dj]);
                        #pragma unroll
                        for (int j = 0; j < 8; ++j) fma2(acc[j], wp, wd[dj + j]);
                    }
                }
                #pragma unroll
                for (int u = 0; u < 7; ++u) wprev[u] = wcur[u];
            }
            #pragma unroll
            for (int j = 0; j < 8; ++j) {
                float2 f = up2(acc[j]);
                int p0 = dc_rr*8 + j;            // row dc_rr
                H[p0*H_P + dc_c]       = f.x;
                H[(p0 + 8)*H_P + dc_c] = f.y;    // row dc_rr+1
            }
        }
        __syncthreads();

        // ---- LayerNorm over 64 pos per channel (staggered, tf32 out) ------
        {
            int ch = t >> 2, q = t & 3;
            float v[16];
            float sum = 0.f, sq = 0.f;
            #pragma unroll
            for (int u = 0; u < 16; ++u) {
                int pos = q*16 + ((u + 2*q) & 15);
                float vv = H[pos*H_P + ch];
                v[u] = vv; sum += vv; sq += vv*vv;
            }
            sum += __shfl_xor_sync(0xFFFFFFFFu, sum, 1);
            sq  += __shfl_xor_sync(0xFFFFFFFFu, sq, 1);
            sum += __shfl_xor_sync(0xFFFFFFFFu, sum, 2);
            sq  += __shfl_xor_sync(0xFFFFFFFFu, sq, 2);
            float mu   = sum * (1.f/64.f);
            float var  = sq  * (1.f/64.f) - mu*mu;
            float rstd = rsqrtf(var + 1e-5f);
            #pragma unroll
            for (int u = 0; u < 16; ++u) {
                int pos = q*16 + ((u + 2*q) & 15);
                float vv = (v[u] - mu) * rstd * __ldg(&ln_w[e*64 + pos])
                           + __ldg(&ln_b[e*64 + pos]);
                H[pos*H_P + ch] = to_tf32(vv);
            }
        }
        __syncthreads();

        // ---- GEMM1 mma: D1[64 x 128(int)] = H x W1(WG) --------------------
        float ac1[8][4];
        {
            #pragma unroll
            for (int jt = 0; jt < 8; ++jt)
                #pragma unroll
                for (int q = 0; q < 4; ++q) ac1[jt][q] = 0.f;

            #pragma unroll
            for (int ks = 0; ks < 8; ++ks) {
                int k0 = ks*8 + tig, k1 = k0 + 4;
                uint32_t a0 = fu(H[r0*H_P + k0]);
                uint32_t a1 = fu(H[r1*H_P + k0]);
                uint32_t a2 = fu(H[r0*H_P + k1]);
                uint32_t a3 = fu(H[r1*H_P + k1]);
                #pragma unroll
                for (int jt = 0; jt < 8; ++jt) {
                    int nb = nh*64 + jt*8 + gid;
                    uint32_t b0 = fu(WG[k0*W1_P + nb]);
                    uint32_t b1 = fu(WG[k1*W1_P + nb]);
                    mma8(ac1[jt], a0, a1, a2, a3, b0, b1);
                }
            }
        }
        __syncthreads();   // all W1 reads done before XG overwrites WG

        // ---- GLU in regs -> XG (aliased over W1 region) -------------------
        {
            const float* bi = pwi_b + e*128;
            #pragma unroll
            for (int jt = 0; jt < 8; ++jt) {
                int o = nh*32 + jt*4 + tig;
                float ba = __ldg(&bi[o]), bg = __ldg(&bi[64 + o]);
                float a = ac1[jt][0] + ba, g = ac1[jt][1] + bg;
                WG[r0*XG_P + o] = to_tf32(a * (1.f/(1.f + __expf(-a))) * g);
                a = ac1[jt][2] + ba; g = ac1[jt][3] + bg;
                WG[r1*XG_P + o] = to_tf32(a * (1.f/(1.f + __expf(-a))) * g);
            }
        }
        __syncthreads();

        // ---- GEMM2: D2[64 x 64] = XG x W2 -> osum (weighted) --------------
        {
            float ac[4][4];
            #pragma unroll
            for (int jt = 0; jt < 4; ++jt)
                #pragma unroll
                for (int q = 0; q < 4; ++q) ac[jt][q] = 0.f;

            #pragma unroll
            for (int ks = 0; ks < 8; ++ks) {
                int k0 = ks*8 + tig, k1 = k0 + 4;
                uint32_t a0 = fu(WG[r0*XG_P + k0]);
                uint32_t a1 = fu(WG[r1*XG_P + k0]);
                uint32_t a2 = fu(WG[r0*XG_P + k1]);
                uint32_t a3 = fu(WG[r1*XG_P + k1]);
                #pragma unroll
                for (int jt = 0; jt < 4; ++jt) {
                    int nb = nh*32 + jt*8 + gid;
                    uint32_t b0 = fu(W2s[k0*W2_P + nb]);
                    uint32_t b1 = fu(W2s[k1*W2_P + nb]);
                    mma8(ac[jt], a0, a1, a2, a3, b0, b1);
                }
            }
            const float* bo = pwo_b + e*64;
            #pragma unroll
            for (int jt = 0; jt < 4; ++jt) {
                int c0 = nh*32 + jt*8 + tig*2;
                float b0 = __ldg(&bo[c0]), b1 = __ldg(&bo[c0+1]);
                osum[jt][0] += we * (ac[jt][0] + b0);
                osum[jt][1] += we * (ac[jt][1] + b1);
                osum[jt][2] += we * (ac[jt][2] + b0);
                osum[jt][3] += we * (ac[jt][3] + b1);
            }
        }
        __syncthreads();   // XG/W2s reads done -> restaging safe
    }

    // ---- out = x + sum_e we*h_e  (residual from persistent xs) -----------
    {
        int i0 = r0 >> 3, j0 = r0 & 7;     // pos r0
        int i1 = r1 >> 3, j1 = r1 & 7;     // pos r1
        #pragma unroll
        for (int jt = 0; jt < 4; ++jt) {
            int c0 = nh*32 + jt*8 + tig*2;
            float x00 = xs[c0*XS_CP     + i0*16 + 3 + j0];
            float x01 = xs[(c0+1)*XS_CP + i0*16 + 3 + j0];
            float x10 = xs[c0*XS_CP     + i1*16 + 3 + j1];
            float x11 = xs[(c0+1)*XS_CP + i1*16 + 3 + j1];
            long idx00 = gbase + (long)c0*131072     + i0*128 + j0;
            long idx01 = gbase + (long)(c0+1)*131072 + i0*128 + j0;
            long idx10 = gbase + (long)c0*131072     + i1*128 + j1;
            long idx11 = gbase + (long)(c0+1)*131072 + i1*128 + j1;
            out[idx00] = x00 + osum[jt][0];
            out[idx01] = x01 + osum[jt][1];
            out[idx10] = x10 + osum[jt][2];
            out[idx11] = x11 + osum[jt][3];
        }
    }
}

// ---------------------------------------------------------------------------
extern "C" void kernel_launch(void* const* d_in, const int* in_sizes, int n_in,
                              void* d_out, int out_size)
{
    const float* x        = (const float*)d_in[0];
    const float* router_w = (const float*)d_in[1];
    const float* router_b = (const float*)d_in[2];
    const float* dw_w     = (const float*)d_in[3];
    const float* dw_b     = (const float*)d_in[4];
    const float* ln_w     = (const float*)d_in[5];
    const float* ln_b     = (const float*)d_in[6];
    const float* pwi_w    = (const float*)d_in[7];
    const float* pwi_b    = (const float*)d_in[8];
    const float* pwo_w    = (const float*)d_in[9];
    const float* pwo_b    = (const float*)d_in[10];
    float* out = (float*)d_out;

    router_kernel<<<NPATCH, 256>>>(x, router_w, router_b, pwi_w, pwo_w);

    const int smem_bytes = SMEM_FLOATS * sizeof(float);   // 104448
    cudaFuncSetAttribute(moe_kernel,
                         cudaFuncAttributeMaxDynamicSharedMemorySize, smem_bytes);
    moe_kernel<<<4096, 256, smem_bytes>>>(x, dw_w, dw_b, ln_w, ln_b,
                                          pwi_b, pwo_b, out);
}

// round 16
// speedup vs baseline: 1.0569x; 1.0229x over previous
#include <cuda_runtime.h>
#include <cstdint>
#include <cmath>

// ---------------------------------------------------------------------------
// SpatialPatchMoE round 16: round-15 base (400.3us) + k-paired float2 operand
// layouts. m16n8k8 consumes k-pairs (ks*8+tig, +4); prepass stores W1/W2
// pre-paired and GLU writes XG pre-paired -> B-fragments and GEMM2 A-fragments
// load as single LDS.64 (conflict-free: pitch ≡ 4 mod 16).
// ---------------------------------------------------------------------------

#define NPATCH 512
typedef unsigned long long ull;

// smem layout (floats)
#define XS_CP   132                  // xs: [64ch][8*16+4] = 8448
#define H_OFF   8448                 // H [64 pos][68] -> 4352
#define H_P     68
#define WG_OFF  12800                // W1p 32rows x 132 float2 = 8448 floats
                                     //   (aliased with XGp 32 x 68 float2 = 4352)
#define W1P2    132                  // pitch in float2 (132 mod 16 = 4)
#define XGP2    68                   // pitch in float2 (68 mod 16 = 4)
#define W2_OFF  21248                // W2p 32 x 68 float2 = 4352 floats
#define W2P2    68
#define SMEM_FLOATS 25600            // 102400 bytes -> 2 blocks/SM

__device__ int   g_topi[NPATCH][2];
__device__ float g_topw[NPATCH][2];
__device__ __align__(16) float g_w1f[8][8448];   // paired W1 (tf32)
__device__ __align__(16) float g_w2f[8][4352];   // paired W2 (tf32)

// ---- f32x2 / tf32 helpers ----
__device__ __forceinline__ ull pk2(float lo, float hi) {
    ull r; asm("mov.b64 %0, {%1, %2};" : "=l"(r) : "f"(lo), "f"(hi)); return r;
}
__device__ __forceinline__ ull dup2(float v) {
    ull r; asm("mov.b64 %0, {%1, %1};" : "=l"(r) : "f"(v)); return r;
}
__device__ __forceinline__ void fma2(ull& d, ull a, ull b) {
    asm("fma.rn.f32x2 %0, %1, %2, %0;" : "+l"(d) : "l"(a), "l"(b));
}
__device__ __forceinline__ float2 up2(ull v) {
    float2 f; asm("mov.b64 {%0, %1}, %2;" : "=f"(f.x), "=f"(f.y) : "l"(v)); return f;
}
__device__ __forceinline__ float to_tf32(float x) {
    uint32_t r; asm("cvt.rna.tf32.f32 %0, %1;" : "=r"(r) : "f"(x));
    return __uint_as_float(r);
}
__device__ __forceinline__ void mma8(float* d, uint32_t a0, uint32_t a1,
                                     uint32_t a2, uint32_t a3,
                                     uint32_t b0, uint32_t b1) {
    asm volatile(
        "mma.sync.aligned.m16n8k8.row.col.f32.tf32.tf32.f32 "
        "{%0,%1,%2,%3}, {%4,%5,%6,%7}, {%8,%9}, {%0,%1,%2,%3};"
        : "+f"(d[0]), "+f"(d[1]), "+f"(d[2]), "+f"(d[3])
        : "r"(a0), "r"(a1), "r"(a2), "r"(a3), "r"(b0), "r"(b1));
}
__device__ __forceinline__ uint32_t fu(float x) { return __float_as_uint(x); }

// ---------------------------------------------------------------------------
// Router + distributed weight prepass (grid 512).
// Pairing: channel c -> row (c>>3)*4 + (c&3), half (c>>2)&1.
// W1 col: np = a/g interleave of o.  W2 col: o.
// ---------------------------------------------------------------------------
__global__ __launch_bounds__(256) void router_kernel(
    const float* __restrict__ x,
    const float* __restrict__ rw,
    const float* __restrict__ rb,
    const float* __restrict__ pwi_w,
    const float* __restrict__ pwo_w)
{
    int n  = blockIdx.x;
    int b  = n >> 8;
    int ph = (n >> 4) & 15;
    int pw = n & 15;
    int t = threadIdx.x, lane = t & 31, warp = t >> 5;
    int i4 = lane >> 3, j = lane & 7;

    // ---- distributed paired prepass ----
    {
        int e = n >> 6, part = n & 63;
        if (t < 128) {
            int i = part*128 + t;                   // W1: 128 elements/block
            int o = i >> 6, c = i & 63;
            int np = (o < 64) ? (2*o) : (2*(o-64) + 1);
            int row = ((c >> 3) << 2) | (c & 3);
            int hi  = (c >> 2) & 1;
            g_w1f[e][row*(W1P2*2) + np*2 + hi] = to_tf32(pwi_w[(long)e*8192 + i]);
        } else if (t < 192) {
            int i = part*64 + (t - 128);            // W2: 64 elements/block
            int o = i >> 6, c = i & 63;
            int row = ((c >> 3) << 2) | (c & 3);
            int hi  = (c >> 2) & 1;
            g_w2f[e][row*(W2P2*2) + o*2 + hi] = to_tf32(pwo_w[(long)e*4096 + i]);
        }
    }

    __shared__ float sm[64];
    __shared__ float logits[8];

    for (int r = 0; r < 8; ++r) {
        int c = warp * 8 + r;
        const float* xc = x + ((long)b*64 + c)*131072 + (ph*8)*128 + pw*8;
        float s = 0.f;
        #pragma unroll
        for (int l = 0; l < 8; ++l) {
            long base = (long)l * 16384;
            s += xc[base + i4*128 + j];
            s += xc[base + (i4+4)*128 + j];
        }
        #pragma unroll
        for (int off = 16; off; off >>= 1) s += __shfl_xor_sync(0xFFFFFFFFu, s, off);
        if (lane == 0) sm[c] = s * (1.f/512.f);
    }
    __syncthreads();
    if (t < 8) {
        float acc = rb[t];
        const float* w = rw + t*64;
        #pragma unroll
        for (int c = 0; c < 64; ++c) acc += sm[c] * w[c];
        logits[t] = acc;
    }
    __syncthreads();
    if (t == 0) {
        int i0 = 0; float v0 = logits[0];
        #pragma unroll
        for (int e = 1; e < 8; ++e) if (logits[e] > v0) { v0 = logits[e]; i0 = e; }
        int i1 = -1; float v1 = -3.4e38f;
        #pragma unroll
        for (int e = 0; e < 8; ++e) if (e != i0 && logits[e] > v1) { v1 = logits[e]; i1 = e; }
        float e1  = __expf(v1 - v0);
        float inv = 1.f / (1.f + e1);
        g_topi[n][0] = i0; g_topi[n][1] = i1;
        g_topw[n][0] = inv; g_topw[n][1] = e1 * inv;
    }
}

// ---------------------------------------------------------------------------
// Main kernel: grid 4096 = (patch, l); 256 threads; 2 blocks/SM.
// ---------------------------------------------------------------------------
extern __shared__ float smem_dyn[];

__global__ __launch_bounds__(256, 2) void moe_kernel(
    const float* __restrict__ x,
    const float* __restrict__ dw_w,  const float* __restrict__ dw_b,
    const float* __restrict__ ln_w,  const float* __restrict__ ln_b,
    const float* __restrict__ pwi_b, const float* __restrict__ pwo_b,
    float* __restrict__ out)
{
    float* xs  = smem_dyn;              // [64ch][132] persists both experts
    float* H   = smem_dyn + H_OFF;      // [64 pos][68]
    float* WG  = smem_dyn + WG_OFF;     // W1p (paired), then XGp (paired)
    float* W2s = smem_dyn + W2_OFF;     // W2p (paired)

    float2* W1p = (float2*)WG;          // [32 rows][pitch 132]
    float2* XGp = (float2*)WG;          // [32 rows][pitch 68]
    float2* W2p = (float2*)W2s;         // [32 rows][pitch 68]

    int s = blockIdx.x;
    int n = s >> 3, l = s & 7;
    int b = n >> 8, ph = (n >> 4) & 15, pwn = n & 15;
    int t = threadIdx.x, lane = t & 31, wid = t >> 5;

    const long gbase = (long)b*64*131072 + (long)l*16384 + (ph*8)*128 + pwn*8;

    int   e0 = g_topi[n][0], e1i = g_topi[n][1];
    float wgt0 = g_topw[n][0], wgt1 = g_topw[n][1];

    // warp MMA tiling
    const int gid = lane >> 2;              // 0..7
    const int tig = lane & 3;               // 0..3
    const int mt  = wid & 3;                // m-tile (16 positions)
    const int nh  = wid >> 2;               // n-half (0..1)
    const int r0  = mt*16 + gid, r1 = r0 + 8;

    // dwconv per-thread assignment
    const int dc_c  = t >> 2;               // channel 0..63
    const int dc_rr = (t & 3) * 2;          // output rows rr, rr+1

    float osum[4][4];
    #pragma unroll
    for (int jt = 0; jt < 4; ++jt)
        #pragma unroll
        for (int q = 0; q < 4; ++q) osum[jt][q] = 0.f;

    // ---- one-time xs load (persists across both experts) ------------------
    for (int rid = t; rid < 512; rid += 256) {
        float* row = xs + (rid >> 3)*XS_CP + (rid & 7)*16;
        row[0] = 0.f; row[1] = 0.f; row[2] = 0.f;
        row[11] = 0.f; row[12] = 0.f; row[13] = 0.f;
    }
    for (int idx = t; idx < 4096; idx += 256) {
        int c = idx >> 6, p = idx & 63, i = p >> 3, j = p & 7;
        xs[c*XS_CP + i*16 + 3 + j] = x[gbase + (long)c*131072 + i*128 + j];
    }

    for (int kk = 0; kk < 2; ++kk) {
        const int   e  = kk ? e1i : e0;
        const float we = kk ? wgt1 : wgt0;

        // ---- stage W1p (2112 float4), W2p (1088 float4) -------------------
        {
            const float4* s1 = (const float4*)g_w1f[e];
            float4* d1 = (float4*)WG;
            #pragma unroll
            for (int i = 0; i < 9; ++i) {             // ceil(2112/256) = 9
                int idx = t + i*256;
                if (idx < 2112) d1[idx] = s1[idx];
            }
            const float4* s2 = (const float4*)g_w2f[e];
            float4* d2 = (float4*)W2s;
            #pragma unroll
            for (int i = 0; i < 5; ++i) {             // ceil(1088/256) = 5
                int idx = t + i*256;
                if (idx < 1088) d2[idx] = s2[idx];
            }
        }
        __syncthreads();   // xs (kk=0) + staging visible

        // ---- dwconv 7x7 (f32x2 over row pair) -> H[pos][ch] ---------------
        {
            const float* W = dw_w + ((long)e*64 + dc_c)*49;
            float bias = __ldg(&dw_b[e*64 + dc_c]);
            ull acc[8];
            #pragma unroll
            for (int j = 0; j < 8; ++j) acc[j] = dup2(bias);

            float wprev[7];
            #pragma unroll
            for (int u = 0; u < 7; ++u) wprev[u] = 0.f;

            #pragma unroll
            for (int di = 0; di < 8; ++di) {
                float wcur[7];
                #pragma unroll
                for (int u = 0; u < 7; ++u)
                    wcur[u] = (di <= 6) ? __ldg(&W[di*7 + u]) : 0.f;
                int ii = dc_rr + di - 3;
                if (ii >= 0 && ii <= 7) {
                    const float* xr = xs + dc_c*XS_CP + ii*16;
                    float4 v0 = *(const float4*)(xr);
                    float4 v1 = *(const float4*)(xr + 4);
                    float4 v2 = *(const float4*)(xr + 8);
                    float4 v3 = *(const float4*)(xr + 12);
                    float win[14] = {v0.x,v0.y,v0.z,v0.w, v1.x,v1.y,v1.z,v1.w,
                                     v2.x,v2.y,v2.z,v2.w, v3.x,v3.y};
                    ull wd[14];
                    #pragma unroll
                    for (int u = 0; u < 14; ++u) wd[u] = dup2(win[u]);
                    #pragma unroll
                    for (int dj = 0; dj < 7; ++dj) {
                        ull wp = pk2(wcur[dj], wprev[dj]);
                        #pragma unroll
                        for (int j = 0; j < 8; ++j) fma2(acc[j], wp, wd[dj + j]);
                    }
                }
                #pragma unroll
                for (int u = 0; u < 7; ++u) wprev[u] = wcur[u];
            }
            #pragma unroll
            for (int j = 0; j < 8; ++j) {
                float2 f = up2(acc[j]);
                int p0 = dc_rr*8 + j;            // row dc_rr
                H[p0*H_P + dc_c]       = f.x;
                H[(p0 + 8)*H_P + dc_c] = f.y;    // row dc_rr+1
            }
        }
        __syncthreads();

        // ---- LayerNorm over 64 pos per channel (staggered, tf32 out) ------
        {
            int ch = t >> 2, q = t & 3;
            float v[16];
            float sum = 0.f, sq = 0.f;
            #pragma unroll
            for (int u = 0; u < 16; ++u) {
                int pos = q*16 + ((u + 2*q) & 15);
                float vv = H[pos*H_P + ch];
                v[u] = vv; sum += vv; sq += vv*vv;
            }
            sum += __shfl_xor_sync(0xFFFFFFFFu, sum, 1);
            sq  += __shfl_xor_sync(0xFFFFFFFFu, sq, 1);
            sum += __shfl_xor_sync(0xFFFFFFFFu, sum, 2);
            sq  += __shfl_xor_sync(0xFFFFFFFFu, sq, 2);
            float mu   = sum * (1.f/64.f);
            float var  = sq  * (1.f/64.f) - mu*mu;
            float rstd = rsqrtf(var + 1e-5f);
            #pragma unroll
            for (int u = 0; u < 16; ++u) {
                int pos = q*16 + ((u + 2*q) & 15);
                float vv = (v[u] - mu) * rstd * __ldg(&ln_w[e*64 + pos])
                           + __ldg(&ln_b[e*64 + pos]);
                H[pos*H_P + ch] = to_tf32(vv);
            }
        }
        __syncthreads();

        // ---- GEMM1: D1[64 x 128(int)] = H x W1p (paired B loads) ----------
        float ac1[8][4];
        {
            #pragma unroll
            for (int jt = 0; jt < 8; ++jt)
                #pragma unroll
                for (int q = 0; q < 4; ++q) ac1[jt][q] = 0.f;

            #pragma unroll
            for (int ks = 0; ks < 8; ++ks) {
                int k0 = ks*8 + tig, k1 = k0 + 4;
                int rb1 = (ks*4 + tig) * W1P2;
                uint32_t a0 = fu(H[r0*H_P + k0]);
                uint32_t a1 = fu(H[r1*H_P + k0]);
                uint32_t a2 = fu(H[r0*H_P + k1]);
                uint32_t a3 = fu(H[r1*H_P + k1]);
                #pragma unroll
                for (int jt = 0; jt < 8; ++jt) {
                    int nb = nh*64 + jt*8 + gid;
                    float2 b01 = W1p[rb1 + nb];
                    mma8(ac1[jt], a0, a1, a2, a3, fu(b01.x), fu(b01.y));
                }
            }
        }
        __syncthreads();   // all W1p reads done before XGp overwrites WG

        // ---- GLU in regs -> XGp (paired over (o, o+4)) --------------------
        {
            const float* bi = pwi_b + e*128;
            #pragma unroll
            for (int m = 0; m < 4; ++m) {
                int o_lo = nh*32 + (2*m)*4 + tig;   // jt = 2m
                int o_hi = o_lo + 4;                // jt = 2m+1
                float balo = __ldg(&bi[o_lo]),     bahi = __ldg(&bi[o_hi]);
                float bglo = __ldg(&bi[64+o_lo]),  bghi = __ldg(&bi[64+o_hi]);
                int row = (nh*4 + m)*4 + tig;

                float a = ac1[2*m][0] + balo, g = ac1[2*m][1] + bglo;
                float vlo0 = a * (1.f/(1.f + __expf(-a))) * g;
                a = ac1[2*m+1][0] + bahi; g = ac1[2*m+1][1] + bghi;
                float vhi0 = a * (1.f/(1.f + __expf(-a))) * g;
                XGp[row*XGP2 + r0] = make_float2(to_tf32(vlo0), to_tf32(vhi0));

                a = ac1[2*m][2] + balo; g = ac1[2*m][3] + bglo;
                float vlo1 = a * (1.f/(1.f + __expf(-a))) * g;
                a = ac1[2*m+1][2] + bahi; g = ac1[2*m+1][3] + bghi;
                float vhi1 = a * (1.f/(1.f + __expf(-a))) * g;
                XGp[row*XGP2 + r1] = make_float2(to_tf32(vlo1), to_tf32(vhi1));
            }
        }
        __syncthreads();

        // ---- GEMM2: D2[64 x 64] = XGp x W2p (all-paired loads) ------------
        {
            float ac[4][4];
            #pragma unroll
            for (int jt = 0; jt < 4; ++jt)
                #pragma unroll
                for (int q = 0; q < 4; ++q) ac[jt][q] = 0.f;

            #pragma unroll
            for (int ks = 0; ks < 8; ++ks) {
                int rb = ks*4 + tig;
                float2 p0 = XGp[rb*XGP2 + r0];   // (A[r0][k0], A[r0][k1])
                float2 p1 = XGp[rb*XGP2 + r1];   // (A[r1][k0], A[r1][k1])
                uint32_t a0 = fu(p0.x), a1 = fu(p1.x);
                uint32_t a2 = fu(p0.y), a3 = fu(p1.y);
                #pragma unroll
                for (int jt = 0; jt < 4; ++jt) {
                    int nb = nh*32 + jt*8 + gid;
                    float2 b01 = W2p[rb*W2P2 + nb];
                    mma8(ac[jt], a0, a1, a2, a3, fu(b01.x), fu(b01.y));
                }
            }
            const float* bo = pwo_b + e*64;
            #pragma unroll
            for (int jt = 0; jt < 4; ++jt) {
                int c0 = nh*32 + jt*8 + tig*2;
                float b0 = __ldg(&bo[c0]), b1 = __ldg(&bo[c0+1]);
                osum[jt][0] += we * (ac[jt][0] + b0);
                osum[jt][1] += we * (ac[jt][1] + b1);
                osum[jt][2] += we * (ac[jt][2] + b0);
                osum[jt][3] += we * (ac[jt][3] + b1);
            }
        }
        __syncthreads();   // XGp/W2p reads done -> restaging safe
    }

    // ---- out = x + sum_e we*h_e  (residual from persistent xs) -----------
    {
        int i0 = r0 >> 3, j0 = r0 & 7;     // pos r0
        int i1 = r1 >> 3, j1 = r1 & 7;     // pos r1
        #pragma unroll
        for (int jt = 0; jt < 4; ++jt) {
            int c0 = nh*32 + jt*8 + tig*2;
            float x00 = xs[c0*XS_CP     + i0*16 + 3 + j0];
            float x01 = xs[(c0+1)*XS_CP + i0*16 + 3 + j0];
            float x10 = xs[c0*XS_CP     + i1*16 + 3 + j1];
            float x11 = xs[(c0+1)*XS_CP + i1*16 + 3 + j1];
            long idx00 = gbase + (long)c0*131072     + i0*128 + j0;
            long idx01 = gbase + (long)(c0+1)*131072 + i0*128 + j0;
            long idx10 = gbase + (long)c0*131072     + i1*128 + j1;
            long idx11 = gbase + (long)(c0+1)*131072 + i1*128 + j1;
            out[idx00] = x00 + osum[jt][0];
            out[idx01] = x01 + osum[jt][1];
            out[idx10] = x10 + osum[jt][2];
            out[idx11] = x11 + osum[jt][3];
        }
    }
}

// ---------------------------------------------------------------------------
extern "C" void kernel_launch(void* const* d_in, const int* in_sizes, int n_in,
                              void* d_out, int out_size)
{
    const float* x        = (const float*)d_in[0];
    const float* router_w = (const float*)d_in[1];
    const float* router_b = (const float*)d_in[2];
    const float* dw_w     = (const float*)d_in[3];
    const float* dw_b     = (const float*)d_in[4];
    const float* ln_w     = (const float*)d_in[5];
    const float* ln_b     = (const float*)d_in[6];
    const float* pwi_w    = (const float*)d_in[7];
    const float* pwi_b    = (const float*)d_in[8];
    const float* pwo_w    = (const float*)d_in[9];
    const float* pwo_b    = (const float*)d_in[10];
    float* out = (float*)d_out;

    router_kernel<<<NPATCH, 256>>>(x, router_w, router_b, pwi_w, pwo_w);

    const int smem_bytes = SMEM_FLOATS * sizeof(float);   // 102400
    cudaFuncSetAttribute(moe_kernel,
                         cudaFuncAttributeMaxDynamicSharedMemorySize, smem_bytes);
    moe_kernel<<<4096, 256, smem_bytes>>>(x, dw_w, dw_b, ln_w, ln_b,
                                          pwi_b, pwo_b, out);
}